// round 1
// baseline (speedup 1.0000x reference)
#include <cuda_runtime.h>
#include <math.h>

#define NB 2
#define NT 2048
#define NC 1024
#define NH 16
#define DH 64
#define NM (NB*NT)   // 4096 rows

// Scratch (allocation-free: __device__ globals). 4 x 16MB.
__device__ float g_Q[(size_t)NM*NC];
__device__ float g_K[(size_t)NM*NC];
__device__ float g_V[(size_t)NM*NC];
__device__ float g_Y[(size_t)NM*NC];

// ---------------------------------------------------------------------------
// SGEMM: C[M,N] = A[M,K] @ W[K,N] + bias,  M=4096, N=K=1024 (fp32)
// mode 0: A = Aext (x), z in {0,1,2} selects (Wq->g_Q, Wk->g_K, Wv->g_V)
// mode 1: A = g_Y, W0/b0 = Wo/bo, C = Cext (d_out)
// ---------------------------------------------------------------------------
#define GBM 128
#define GBN 128
#define GBK 8

__global__ __launch_bounds__(256)
void sgemm_bias_kernel(const float* __restrict__ Aext,
                       const float* __restrict__ W0, const float* __restrict__ W1,
                       const float* __restrict__ W2,
                       const float* __restrict__ b0, const float* __restrict__ b1,
                       const float* __restrict__ b2,
                       float* __restrict__ Cext, int mode)
{
    const int M = NM, N = NC, K = NC;
    const float* A; const float* W; const float* bias; float* C;
    int z = blockIdx.z;
    if (mode == 0) {
        A = Aext;
        W    = (z == 0) ? W0 : (z == 1) ? W1 : W2;
        bias = (z == 0) ? b0 : (z == 1) ? b1 : b2;
        C    = (z == 0) ? g_Q : (z == 1) ? g_K : g_V;
    } else {
        A = g_Y; W = W0; bias = b0; C = Cext;
    }

    __shared__ float As[GBK][GBM];
    __shared__ float Bs[GBK][GBN];

    int tid = threadIdx.x;
    int bx = blockIdx.x, by = blockIdx.y;

    float acc[8][8];
#pragma unroll
    for (int i = 0; i < 8; i++)
#pragma unroll
        for (int j = 0; j < 8; j++) acc[i][j] = 0.0f;

    const float* Ab = A + (size_t)by * GBM * K;
    const float* Wb = W + (size_t)bx * GBN;

    int arow = tid >> 1, acol = (tid & 1) * 4;   // A tile 128x8 via float4
    int brow = tid >> 5, bcol = (tid & 31) * 4;  // B tile 8x128 via float4
    int rg = (tid >> 4) * 8;                     // thread row offset in tile
    int cg = (tid & 15) * 8;                     // thread col offset in tile

    for (int kt = 0; kt < K; kt += GBK) {
        float4 av = *(const float4*)(Ab + (size_t)arow * K + kt + acol);
        float4 bv = *(const float4*)(Wb + (size_t)(kt + brow) * N + bcol);
        __syncthreads();  // previous compute done before smem overwrite
        As[acol + 0][arow] = av.x;
        As[acol + 1][arow] = av.y;
        As[acol + 2][arow] = av.z;
        As[acol + 3][arow] = av.w;
        *(float4*)&Bs[brow][bcol] = bv;
        __syncthreads();
#pragma unroll
        for (int k = 0; k < GBK; k++) {
            float ra[8], rb[8];
            *(float4*)&ra[0] = *(const float4*)&As[k][rg];
            *(float4*)&ra[4] = *(const float4*)&As[k][rg + 4];
            *(float4*)&rb[0] = *(const float4*)&Bs[k][cg];
            *(float4*)&rb[4] = *(const float4*)&Bs[k][cg + 4];
#pragma unroll
            for (int i = 0; i < 8; i++)
#pragma unroll
                for (int j = 0; j < 8; j++)
                    acc[i][j] += ra[i] * rb[j];
        }
    }

    size_t row0 = (size_t)by * GBM + rg;
    int col0 = bx * GBN + cg;
#pragma unroll
    for (int i = 0; i < 8; i++) {
#pragma unroll
        for (int j = 0; j < 8; j += 4) {
            float4 o;
            o.x = acc[i][j + 0] + bias[col0 + j + 0];
            o.y = acc[i][j + 1] + bias[col0 + j + 1];
            o.z = acc[i][j + 2] + bias[col0 + j + 2];
            o.w = acc[i][j + 3] + bias[col0 + j + 3];
            *(float4*)(C + (row0 + i) * N + col0 + j) = o;
        }
    }
}

// ---------------------------------------------------------------------------
// Flash attention (non-causal, online softmax), fp32.
// Block: 128 threads, BQ=64 queries, BK=32 keys/tile, HD=64.
// Thread (ty=tid/8, tx=tid%8): S rows ty*4+i, S keys tx+8j (j<4),
// O cols tx*8+j (j<8). K-tile and P-tile alias one smem buffer (2112 floats).
// ---------------------------------------------------------------------------
#define FBQ 64
#define FBK 32
#define QP 65   // Qs pitch: 4*65=260 == 4 mod 32 -> conflict-free 4-addr reads
#define KP 66   // K pitch:  66 == 2 mod 32 -> 8 tx stride-2 banks, conflict-free
#define SP 33   // S pitch:  4*33=132 == 4 mod 32 -> conflict-free

__global__ __launch_bounds__(128)
void flash_kernel()
{
    __shared__ float Qs[FBQ][QP];     // 16640 B
    __shared__ float KS[2112];        // union: K[32][66] / P[64][33], 8448 B
    __shared__ float Vs[FBK][DH];     // 8192 B    (total 33280 B)

    int tid = threadIdx.x;
    int qt = blockIdx.x;              // query tile 0..31
    int bh = blockIdx.y;              // 0..31
    int b = bh >> 4, h = bh & 15;

    const float* Qg = g_Q + (size_t)b * NT * NC + h * DH;
    const float* Kg = g_K + (size_t)b * NT * NC + h * DH;
    const float* Vg = g_V + (size_t)b * NT * NC + h * DH;

    int ty = tid >> 3;   // 0..15
    int tx = tid & 7;    // 0..7
    int ty4 = ty * 4;

    // Load Q tile, pre-scaled by 1/sqrt(HD)=0.125
    {
        int lq = tid >> 4;          // 0..7
        int d  = (tid & 15) * 4;
#pragma unroll
        for (int r = 0; r < 8; r++) {
            int q = lq + r * 8;
            float4 v = *(const float4*)(Qg + (size_t)(qt * FBQ + q) * NC + d);
            Qs[q][d + 0] = v.x * 0.125f;
            Qs[q][d + 1] = v.y * 0.125f;
            Qs[q][d + 2] = v.z * 0.125f;
            Qs[q][d + 3] = v.w * 0.125f;
        }
    }

    float oa[4][8];
    float m_r[4], l_r[4];
#pragma unroll
    for (int i = 0; i < 4; i++) {
        m_r[i] = -1e30f; l_r[i] = 0.0f;
#pragma unroll
        for (int c = 0; c < 8; c++) oa[i][c] = 0.0f;
    }

    for (int kt = 0; kt < NT / FBK; kt++) {
        const float* Kt = Kg + (size_t)(kt * FBK) * NC;
        const float* Vt = Vg + (size_t)(kt * FBK) * NC;

        __syncthreads();  // prior O-accum reads of KS/Vs complete
        {
            int lk = tid >> 4;          // 0..7
            int d  = (tid & 15) * 4;
#pragma unroll
            for (int r = 0; r < 4; r++) {
                int key = lk + r * 8;   // 0..31
                float4 kv = *(const float4*)(Kt + (size_t)key * NC + d);
                float* Kp = &KS[key * KP + d];
                Kp[0] = kv.x; Kp[1] = kv.y; Kp[2] = kv.z; Kp[3] = kv.w;
                float4 vv = *(const float4*)(Vt + (size_t)key * NC + d);
                *(float4*)&Vs[key][d] = vv;
            }
        }
        __syncthreads();  // tiles visible

        // S = (Q*0.125) @ K^T  (64x32)
        float s[4][4];
#pragma unroll
        for (int i = 0; i < 4; i++)
#pragma unroll
            for (int j = 0; j < 4; j++) s[i][j] = 0.0f;

#pragma unroll 4
        for (int d = 0; d < DH; d++) {
            float rq[4], rk[4];
#pragma unroll
            for (int i = 0; i < 4; i++) rq[i] = Qs[ty4 + i][d];
#pragma unroll
            for (int j = 0; j < 4; j++) rk[j] = KS[(tx + 8 * j) * KP + d];
#pragma unroll
            for (int i = 0; i < 4; i++)
#pragma unroll
                for (int j = 0; j < 4; j++)
                    s[i][j] += rq[i] * rk[j];
        }
        __syncthreads();  // all K reads done before KS is reused for P

        // Online softmax (per row, reduced across the 8 tx lanes)
        float p[4][4], corr[4], rsum[4];
#pragma unroll
        for (int i = 0; i < 4; i++) {
            float tm = fmaxf(fmaxf(s[i][0], s[i][1]), fmaxf(s[i][2], s[i][3]));
            tm = fmaxf(tm, __shfl_xor_sync(0xffffffffu, tm, 1));
            tm = fmaxf(tm, __shfl_xor_sync(0xffffffffu, tm, 2));
            tm = fmaxf(tm, __shfl_xor_sync(0xffffffffu, tm, 4));
            float mnew = fmaxf(m_r[i], tm);
            corr[i] = __expf(m_r[i] - mnew);
            float rs = 0.0f;
#pragma unroll
            for (int j = 0; j < 4; j++) {
                p[i][j] = __expf(s[i][j] - mnew);
                rs += p[i][j];
            }
            rs += __shfl_xor_sync(0xffffffffu, rs, 1);
            rs += __shfl_xor_sync(0xffffffffu, rs, 2);
            rs += __shfl_xor_sync(0xffffffffu, rs, 4);
            rsum[i] = rs;
            m_r[i] = mnew;
        }
#pragma unroll
        for (int i = 0; i < 4; i++) {
            l_r[i] = l_r[i] * corr[i] + rsum[i];
#pragma unroll
            for (int c = 0; c < 8; c++) oa[i][c] *= corr[i];
        }

        // Store P into KS (as [64][33])
#pragma unroll
        for (int i = 0; i < 4; i++)
#pragma unroll
            for (int j = 0; j < 4; j++)
                KS[(ty4 + i) * SP + (tx + 8 * j)] = p[i][j];
        __syncthreads();

        // O += P @ V
#pragma unroll 4
        for (int k = 0; k < FBK; k++) {
            float rs[4];
#pragma unroll
            for (int i = 0; i < 4; i++) rs[i] = KS[(ty4 + i) * SP + k];
            float4 v0 = *(const float4*)&Vs[k][tx * 8];
            float4 v1 = *(const float4*)&Vs[k][tx * 8 + 4];
#pragma unroll
            for (int i = 0; i < 4; i++) {
                oa[i][0] += rs[i] * v0.x;
                oa[i][1] += rs[i] * v0.y;
                oa[i][2] += rs[i] * v0.z;
                oa[i][3] += rs[i] * v0.w;
                oa[i][4] += rs[i] * v1.x;
                oa[i][5] += rs[i] * v1.y;
                oa[i][6] += rs[i] * v1.z;
                oa[i][7] += rs[i] * v1.w;
            }
        }
    }

    // Normalize and write to g_Y in (B,T,C) layout
#pragma unroll
    for (int i = 0; i < 4; i++) {
        float inv = 1.0f / l_r[i];
        size_t row = (size_t)b * NT + qt * FBQ + ty4 + i;
        float* Yp = g_Y + row * NC + h * DH + tx * 8;
        float4 o0, o1;
        o0.x = oa[i][0] * inv; o0.y = oa[i][1] * inv;
        o0.z = oa[i][2] * inv; o0.w = oa[i][3] * inv;
        o1.x = oa[i][4] * inv; o1.y = oa[i][5] * inv;
        o1.z = oa[i][6] * inv; o1.w = oa[i][7] * inv;
        *(float4*)Yp = o0;
        *(float4*)(Yp + 4) = o1;
    }
}

// ---------------------------------------------------------------------------
extern "C" void kernel_launch(void* const* d_in, const int* in_sizes, int n_in,
                              void* d_out, int out_size)
{
    const float* x  = (const float*)d_in[0];
    const float* Wq = (const float*)d_in[1];
    const float* bq = (const float*)d_in[2];
    const float* Wk = (const float*)d_in[3];
    const float* bk = (const float*)d_in[4];
    const float* Wv = (const float*)d_in[5];
    const float* bv = (const float*)d_in[6];
    const float* Wo = (const float*)d_in[7];
    const float* bo = (const float*)d_in[8];
    float* out = (float*)d_out;

    dim3 gQKV(NC / GBN, NM / GBM, 3);   // 8 x 32 x 3
    sgemm_bias_kernel<<<gQKV, 256>>>(x, Wq, Wk, Wv, bq, bk, bv, nullptr, 0);

    dim3 gAtt(NT / FBQ, NB * NH);       // 32 x 32
    flash_kernel<<<gAtt, 128>>>();

    dim3 gOut(NC / GBN, NM / GBM, 1);   // 8 x 32
    sgemm_bias_kernel<<<gOut, 256>>>(x, Wo, nullptr, nullptr, bo, nullptr, nullptr, out, 1);
}